// round 14
// baseline (speedup 1.0000x reference)
#include <cuda_runtime.h>
#include <cuda_bf16.h>

#define BB 64
#define VV 64
#define TT 256
#define FF 64
#define AP  68    // adj row pitch: 16B-aligned, LDS.128 conflict-free (68 mod 32 = 4)

__device__ float g_xt[TT * BB * VV];      // Xt[t][b][w]   (4 MB)
__device__ float g_hagg[BB * TT * VV];    // H_agg[b][t][v] (4 MB)

// fast sigmoid: 1 MUFU + bit-trick rcp + 2 Newton (rel ~1e-6, validated R11/R13)
__device__ __forceinline__ float fsig(float a) {
    float e = __expf(-a);
    float d = 1.0f + e;
    float y = __uint_as_float(0x7EF311C3u - __float_as_uint(d));
    y = y * (2.0f - d * y);
    y = y * (2.0f - d * y);
    return y;
}

// ---------------------------------------------------------------------------
// k0: Xt[t][b][w] = X[b][w][t]  (both sides coalesced; ~1 us)
// ---------------------------------------------------------------------------
__global__ __launch_bounds__(256)
void k0_xt(const float* __restrict__ X, float* __restrict__ Xt)
{
    __shared__ float st[64][65];
    const int tc  = blockIdx.x;         // 0..3
    const int b   = blockIdx.y;         // 0..63
    const int tid = threadIdx.x;

    #pragma unroll
    for (int k = 0; k < 16; ++k) {
        int i  = tid + k * 256;
        int w  = i >> 6, tl = i & 63;
        st[tl][w] = X[(size_t)b * (VV * TT) + (size_t)w * TT + tc * 64 + tl];
    }
    __syncthreads();

    float4* Ot = reinterpret_cast<float4*>(Xt);
    #pragma unroll
    for (int k = 0; k < 4; ++k) {
        int i  = tid + k * 256;
        int tl = i >> 4, w4 = i & 15;
        float4 v = make_float4(st[tl][w4 * 4 + 0], st[tl][w4 * 4 + 1],
                               st[tl][w4 * 4 + 2], st[tl][w4 * 4 + 3]);
        Ot[(size_t)(tc * 64 + tl) * (BB * VV / 4) + b * (VV / 4) + w4] = v;
    }
}

// ---------------------------------------------------------------------------
// k1: H_agg. Block = (bc16, t): 16 batches, one t (A redundancy 4x, L2-hot).
// Warp wid owns rows wid and wid+8; results go register->global (coalesced),
// no hs smem, ONE barrier total.
// ---------------------------------------------------------------------------
__global__ __launch_bounds__(256, 8)
void k1_hagg(const float* __restrict__ Xt,
             const float* __restrict__ A,
             float* __restrict__ hout)
{
    __shared__ float adj[VV][AP];       // 17.4 KB
    __shared__ float xs[16][VV];        // 4 KB

    const int bc  = blockIdx.x;         // 0..3 (fast: same-t blocks adjacent)
    const int t   = blockIdx.y;         // 0..255
    const int tid = threadIdx.x;
    const int wid = tid >> 5;           // 0..7
    const int lid = tid & 31;
    const int b0  = bc * 16;

    // adj = fsig(A_t) off-diag, 1 on diag
    const float4* Ag = reinterpret_cast<const float4*>(A + (size_t)t * VV * VV);
    #pragma unroll 2
    for (int k = 0; k < 4; ++k) {
        int i  = tid + k * 256;
        int v  = i >> 4;
        int w4 = i & 15;
        float4 a = Ag[i];
        float4 s;
        s.x = fsig(a.x); s.y = fsig(a.y); s.z = fsig(a.z); s.w = fsig(a.w);
        int wbase = w4 * 4;
        if (v == wbase + 0) s.x = 1.0f;
        if (v == wbase + 1) s.y = 1.0f;
        if (v == wbase + 2) s.z = 1.0f;
        if (v == wbase + 3) s.w = 1.0f;
        *reinterpret_cast<float4*>(&adj[v][wbase]) = s;
    }

    // xs: contiguous 4 KB slab Xt[t][b0..b0+15][:]  (256 f4, 1/thread)
    {
        const float4* src = reinterpret_cast<const float4*>(
            Xt + ((size_t)t * BB + b0) * VV);
        float4 v = src[tid];
        int bl = tid >> 4, w4 = tid & 15;
        *reinterpret_cast<float4*>(&xs[bl][w4 * 4]) = v;
    }
    __syncthreads();

    // two warp-private dots; store straight from registers (coalesced 128B x2)
    #pragma unroll
    for (int half = 0; half < 2; ++half) {
        const int r = wid + half * 8;
        float s0 = 0.f, s1 = 0.f;
        #pragma unroll
        for (int w4 = 0; w4 < 16; ++w4) {
            float4 p = *reinterpret_cast<const float4*>(&adj[lid     ][w4 * 4]);
            float4 q = *reinterpret_cast<const float4*>(&adj[lid + 32][w4 * 4]);
            float4 x = *reinterpret_cast<const float4*>(&xs[r][w4 * 4]);
            s0 = fmaf(p.x, x.x, s0); s0 = fmaf(p.y, x.y, s0);
            s0 = fmaf(p.z, x.z, s0); s0 = fmaf(p.w, x.w, s0);
            s1 = fmaf(q.x, x.x, s1); s1 = fmaf(q.y, x.y, s1);
            s1 = fmaf(q.z, x.z, s1); s1 = fmaf(q.w, x.w, s1);
        }
        float* dst = hout + ((size_t)(b0 + r) * TT + t) * VV;
        dst[lid]      = s0;
        dst[lid + 32] = s1;
    }
}

// ---------------------------------------------------------------------------
// k2: expansion (structure of the MEASURED 41.3us kernel + hoisted W).
// Block bt streams one contiguous 16 KB row; linear bt sweep.
// ---------------------------------------------------------------------------
__global__ __launch_bounds__(256)
void k2_expand(const float* __restrict__ hagg,
               const float* __restrict__ W,
               float* __restrict__ out)
{
    __shared__ float hs[VV];

    const int bt  = blockIdx.x;
    const int tid = threadIdx.x;

    if (tid < VV) hs[tid] = hagg[(size_t)bt * VV + tid];
    const float4 wv = reinterpret_cast<const float4*>(W)[tid & 15];
    __syncthreads();

    float4* o = reinterpret_cast<float4*>(out + (size_t)bt * (VV * FF));
    #pragma unroll
    for (int j = 0; j < (VV * FF / 4) / 256; ++j) {   // 4 iterations
        int p = j * 256 + tid;
        float h = hs[p >> 4];
        float4 r;
        r.x = h * wv.x; r.y = h * wv.y; r.z = h * wv.z; r.w = h * wv.w;
        r.x = fmaxf(r.x, 0.01f * r.x);
        r.y = fmaxf(r.y, 0.01f * r.y);
        r.z = fmaxf(r.z, 0.01f * r.z);
        r.w = fmaxf(r.w, 0.01f * r.w);
        __stcs(&o[p], r);
    }
}

extern "C" void kernel_launch(void* const* d_in, const int* in_sizes, int n_in,
                              void* d_out, int out_size) {
    const float* X = (const float*)d_in[0];   // [64, 64, 256]
    const float* A = (const float*)d_in[1];   // [256, 64, 64]
    const float* W = (const float*)d_in[2];   // [64, 1]
    float* out = (float*)d_out;               // [64, 256, 4096]
    (void)in_sizes; (void)n_in; (void)out_size;

    float *xt, *hagg;
    cudaGetSymbolAddress((void**)&xt,   g_xt);
    cudaGetSymbolAddress((void**)&hagg, g_hagg);

    dim3 g0(TT / 64, BB);                     // (4, 64)
    k0_xt<<<g0, 256>>>(X, xt);

    dim3 g1(4, TT);                           // (4, 256)
    k1_hagg<<<g1, 256>>>(xt, A, hagg);

    k2_expand<<<BB * TT, 256>>>(hagg, W, out);
}

// round 15
// speedup vs baseline: 1.0019x; 1.0019x over previous
#include <cuda_runtime.h>
#include <cuda_bf16.h>

#define BB 64
#define VV 64
#define TT 256
#define FF 64
#define AP  68    // adj row pitch: 16B-aligned, LDS.128 conflict-free (68 mod 32 = 4)

__device__ float g_hagg[BB * TT * VV];    // H_agg[b][t][v] (4 MB)

// fast sigmoid: 1 MUFU + bit-trick rcp + 2 Newton (rel ~1e-6, validated R11/R13)
__device__ __forceinline__ float fsig(float a) {
    float e = __expf(-a);
    float d = 1.0f + e;
    float y = __uint_as_float(0x7EF311C3u - __float_as_uint(d));
    y = y * (2.0f - d * y);
    y = y * (2.0f - d * y);
    return y;
}

// ---------------------------------------------------------------------------
// k1: H_agg for 16 batches x 2 timesteps per block. grid (4,128) = 512 blocks,
// 4 CTAs/SM (smem 43KB) = one balanced wave. X staged via float2 (t0,t0+1
// contiguous) — full-8B sectors, no transpose kernel needed.
// Warp wid owns b in {2wid, 2wid+1}; lane owns v = lid and lid+32; 8 acc.
// ---------------------------------------------------------------------------
__global__ __launch_bounds__(256, 4)
void k1_hagg(const float* __restrict__ X,
             const float* __restrict__ A,
             float* __restrict__ hout)
{
    __shared__ float adj2[2][VV][AP];   // 34.8 KB (two t-tiles)
    __shared__ float xs[16][VV][2];     // 8 KB: xs[b][w][tsel]

    const int bc  = blockIdx.x;         // 0..3 (fast: same-t blocks adjacent, A L2-hot)
    const int tp  = blockIdx.y;         // 0..127
    const int t0  = tp * 2;
    const int tid = threadIdx.x;
    const int wid = tid >> 5;           // 0..7
    const int lid = tid & 31;
    const int b0  = bc * 16;

    // ---- adj for both t's: 2048 float4, 8/thread ----
    #pragma unroll
    for (int k = 0; k < 8; ++k) {
        int i  = tid + k * 256;         // 0..2047
        int tl = i >> 10;               // which t-tile
        int j  = i & 1023;              // f4 index within tile
        int v  = j >> 4, w4 = j & 15;
        float4 a = reinterpret_cast<const float4*>(
            A + (size_t)(t0 + tl) * VV * VV)[j];
        float4 s;
        s.x = fsig(a.x); s.y = fsig(a.y); s.z = fsig(a.z); s.w = fsig(a.w);
        int wbase = w4 * 4;
        if (v == wbase + 0) s.x = 1.0f;
        if (v == wbase + 1) s.y = 1.0f;
        if (v == wbase + 2) s.z = 1.0f;
        if (v == wbase + 3) s.w = 1.0f;
        *reinterpret_cast<float4*>(&adj2[tl][v][wbase]) = s;
    }

    // ---- stage xs: 1024 float2 loads (X[b][w][t0], X[b][w][t0+1] contiguous) ----
    #pragma unroll
    for (int k = 0; k < 4; ++k) {
        int i  = tid + k * 256;         // 0..1023
        int bl = i >> 6, w = i & 63;
        float2 xv = *reinterpret_cast<const float2*>(
            X + ((size_t)(b0 + bl) * VV + w) * TT + t0);   // 8B aligned (t0 even)
        *reinterpret_cast<float2*>(&xs[bl][w][0]) = xv;
    }
    __syncthreads();

    // ---- dots: 8 accumulators [bsel][tsel][vsel] per lane ----
    float acc[2][2][2];
    #pragma unroll
    for (int i = 0; i < 2; ++i)
        #pragma unroll
        for (int j = 0; j < 2; ++j) { acc[i][j][0] = 0.f; acc[i][j][1] = 0.f; }

    #pragma unroll
    for (int w4 = 0; w4 < 16; ++w4) {
        float pa[2][4], qa[2][4];       // adj rows v=lid / v=lid+32, both t's
        *reinterpret_cast<float4*>(pa[0]) =
            *reinterpret_cast<const float4*>(&adj2[0][lid][w4 * 4]);      // conflict-free
        *reinterpret_cast<float4*>(pa[1]) =
            *reinterpret_cast<const float4*>(&adj2[1][lid][w4 * 4]);
        *reinterpret_cast<float4*>(qa[0]) =
            *reinterpret_cast<const float4*>(&adj2[0][lid + 32][w4 * 4]);
        *reinterpret_cast<float4*>(qa[1]) =
            *reinterpret_cast<const float4*>(&adj2[1][lid + 32][w4 * 4]);
        #pragma unroll
        for (int bs = 0; bs < 2; ++bs) {
            const int b = 2 * wid + bs;
            #pragma unroll
            for (int ww = 0; ww < 4; ++ww) {
                float2 xv = *reinterpret_cast<const float2*>(
                    &xs[b][w4 * 4 + ww][0]);                 // warp broadcast
                acc[bs][0][0] = fmaf(pa[0][ww], xv.x, acc[bs][0][0]);
                acc[bs][1][0] = fmaf(pa[1][ww], xv.y, acc[bs][1][0]);
                acc[bs][0][1] = fmaf(qa[0][ww], xv.x, acc[bs][0][1]);
                acc[bs][1][1] = fmaf(qa[1][ww], xv.y, acc[bs][1][1]);
            }
        }
    }

    // ---- register -> global, coalesced 128B groups ----
    #pragma unroll
    for (int bs = 0; bs < 2; ++bs) {
        const int b = b0 + 2 * wid + bs;
        #pragma unroll
        for (int ts = 0; ts < 2; ++ts) {
            float* dst = hout + ((size_t)b * TT + (t0 + ts)) * VV;
            dst[lid]      = acc[bs][ts][0];
            dst[lid + 32] = acc[bs][ts][1];
        }
    }
}

// ---------------------------------------------------------------------------
// k2: expansion — the MEASURED 41.3us structure (R4 + hoisted W).
// ---------------------------------------------------------------------------
__global__ __launch_bounds__(256)
void k2_expand(const float* __restrict__ hagg,
               const float* __restrict__ W,
               float* __restrict__ out)
{
    __shared__ float hs[VV];

    const int bt  = blockIdx.x;
    const int tid = threadIdx.x;

    if (tid < VV) hs[tid] = hagg[(size_t)bt * VV + tid];
    const float4 wv = reinterpret_cast<const float4*>(W)[tid & 15];
    __syncthreads();

    float4* o = reinterpret_cast<float4*>(out + (size_t)bt * (VV * FF));
    #pragma unroll
    for (int j = 0; j < (VV * FF / 4) / 256; ++j) {   // 4 iterations
        int p = j * 256 + tid;
        float h = hs[p >> 4];
        float4 r;
        r.x = h * wv.x; r.y = h * wv.y; r.z = h * wv.z; r.w = h * wv.w;
        r.x = fmaxf(r.x, 0.01f * r.x);
        r.y = fmaxf(r.y, 0.01f * r.y);
        r.z = fmaxf(r.z, 0.01f * r.z);
        r.w = fmaxf(r.w, 0.01f * r.w);
        __stcs(&o[p], r);
    }
}

extern "C" void kernel_launch(void* const* d_in, const int* in_sizes, int n_in,
                              void* d_out, int out_size) {
    const float* X = (const float*)d_in[0];   // [64, 64, 256]
    const float* A = (const float*)d_in[1];   // [256, 64, 64]
    const float* W = (const float*)d_in[2];   // [64, 1]
    float* out = (float*)d_out;               // [64, 256, 4096]
    (void)in_sizes; (void)n_in; (void)out_size;

    float* hagg;
    cudaGetSymbolAddress((void**)&hagg, g_hagg);

    dim3 g1(4, TT / 2);                       // (4, 128) = 512 blocks, one wave
    k1_hagg<<<g1, 256>>>(X, A, hagg);

    k2_expand<<<BB * TT, 256>>>(hagg, W, out);
}

// round 16
// speedup vs baseline: 1.1192x; 1.1171x over previous
#include <cuda_runtime.h>
#include <cuda_bf16.h>

#define BB 64
#define VV 64
#define TT 256
#define FF 64
#define NT  256
#define BPB 8     // one warp per batch row
#define AP  68    // adj row pitch: 272B, 16B-aligned; LDS.128 conflict-free (68 mod 32 = 4)

// fast sigmoid: 1 MUFU (EX2) + bit-trick reciprocal + 2 Newton steps.
// rel err ~1e-6, bench-validated (R11/R13/R14/R15: rel_err 3.4e-6 << 1e-3).
__device__ __forceinline__ float fsig(float a) {
    float e = __expf(-a);
    float d = 1.0f + e;
    float y = __uint_as_float(0x7EF311C3u - __float_as_uint(d));
    y = y * (2.0f - d * y);
    y = y * (2.0f - d * y);
    return y;
}

// ---------------------------------------------------------------------------
// R9 champion structure, verbatim, + fsig.
// Block = (t, bc): one timestep, 8 batches. ONE block barrier.
//  Stage:  adj = fsig(A_t)*(1-I)+I (LDG.128/STS.128); xs[bl][w] = X[b,w,t]
//  Warp wid: dot (LDS.128 conflict-free) -> streams own 16KB row (__stcs).
// ---------------------------------------------------------------------------
__global__ __launch_bounds__(NT)
void gnn_fused(const float* __restrict__ X,
               const float* __restrict__ A,
               const float* __restrict__ W,
               float* __restrict__ out)
{
    __shared__ float adj[VV][AP];       // 17.4 KB
    __shared__ float xs[BPB][VV];       // 2 KB
    __shared__ float hs[BPB][VV];       // 2 KB

    const int t   = blockIdx.x;         // 0..255
    const int bc  = blockIdx.y;         // 0..7
    const int tid = threadIdx.x;
    const int wid = tid >> 5;           // 0..7 == bl
    const int lid = tid & 31;
    const int b0  = bc * BPB;

    // ---- adj = fsig(A_t) off-diag, 1 on diag; 4x float4 per thread ----
    const float4* Ag = reinterpret_cast<const float4*>(A + (size_t)t * VV * VV);
    #pragma unroll
    for (int k = 0; k < 4; ++k) {
        int i  = tid + k * NT;          // float4 index 0..1023, coalesced
        int v  = i >> 4;
        int w4 = i & 15;
        float4 a = Ag[i];
        float4 s;
        s.x = fsig(a.x); s.y = fsig(a.y); s.z = fsig(a.z); s.w = fsig(a.w);
        int wbase = w4 * 4;
        if (v == wbase + 0) s.x = 1.0f;
        if (v == wbase + 1) s.y = 1.0f;
        if (v == wbase + 2) s.z = 1.0f;
        if (v == wbase + 3) s.w = 1.0f;
        *reinterpret_cast<float4*>(&adj[v][wbase]) = s;
    }

    // ---- stage xs[bl][w] = X[b0+bl, w, t] ----
    #pragma unroll
    for (int k = 0; k < (BPB * VV) / NT; ++k) {      // 2 iters
        int i  = tid + k * NT;
        int bl = i >> 6, w = i & 63;
        xs[bl][w] = X[((size_t)(b0 + bl) * VV + w) * TT + t];
    }

    // f index per lane is invariant: p mod 16 == lid mod 16
    const float4 wv = reinterpret_cast<const float4*>(W)[lid & 15];

    __syncthreads();                    // ONLY block-wide barrier

    // ---- warp-private dot: lane owns v=lid and v+32 of row bl=wid ----
    {
        float s0 = 0.f, s1 = 0.f;
        #pragma unroll
        for (int w4 = 0; w4 < 16; ++w4) {
            float4 p = *reinterpret_cast<const float4*>(&adj[lid     ][w4 * 4]); // conflict-free
            float4 q = *reinterpret_cast<const float4*>(&adj[lid + 32][w4 * 4]); // conflict-free
            float4 x = *reinterpret_cast<const float4*>(&xs[wid][w4 * 4]);       // warp bcast
            s0 = fmaf(p.x, x.x, s0); s0 = fmaf(p.y, x.y, s0);
            s0 = fmaf(p.z, x.z, s0); s0 = fmaf(p.w, x.w, s0);
            s1 = fmaf(q.x, x.x, s1); s1 = fmaf(q.y, x.y, s1);
            s1 = fmaf(q.z, x.z, s1); s1 = fmaf(q.w, x.w, s1);
        }
        hs[wid][lid]      = s0;
        hs[wid][lid + 32] = s1;
    }
    __syncwarp();                       // warp-local: hs[wid] visible to own warp

    // ---- warp streams its own 16 KB row; no block barrier -> de-staggered ----
    float4* o = reinterpret_cast<float4*>(
        out + ((size_t)(b0 + wid) * TT + t) * (VV * FF));
    #pragma unroll 8
    for (int j = 0; j < (VV * FF / 4) / 32; ++j) {   // 32 iters
        int p = j * 32 + lid;                        // float4 idx, coalesced per warp
        float h = hs[wid][p >> 4];                   // 2 distinct addrs/warp: bcast
        float4 r;
        r.x = h * wv.x; r.y = h * wv.y; r.z = h * wv.z; r.w = h * wv.w;
        r.x = fmaxf(r.x, 0.01f * r.x);               // leaky: max(x, .01x) both signs
        r.y = fmaxf(r.y, 0.01f * r.y);
        r.z = fmaxf(r.z, 0.01f * r.z);
        r.w = fmaxf(r.w, 0.01f * r.w);
        __stcs(&o[p], r);                            // evict-first stream
    }
}

extern "C" void kernel_launch(void* const* d_in, const int* in_sizes, int n_in,
                              void* d_out, int out_size) {
    const float* X = (const float*)d_in[0];   // [64, 64, 256]
    const float* A = (const float*)d_in[1];   // [256, 64, 64]
    const float* W = (const float*)d_in[2];   // [64, 1]
    float* out = (float*)d_out;               // [64, 256, 4096]
    (void)in_sizes; (void)n_in; (void)out_size;

    dim3 grid(TT, BB / BPB);                  // (256, 8) = 2048 blocks (R9 config)
    gnn_fused<<<grid, NT>>>(X, A, W, out);
}

// round 17
// speedup vs baseline: 1.1349x; 1.0141x over previous
#include <cuda_runtime.h>
#include <cuda_bf16.h>

#define BB 64
#define VV 64
#define TT 256
#define FF 64
#define NT  256
#define BPB 8     // one warp per batch row
#define AP  68    // adj row pitch: 272B, 16B-aligned; LDS.128 conflict-free (68 mod 32 = 4)

// fast sigmoid: 1 MUFU (EX2) + bit-trick reciprocal + 2 Newton steps.
// rel err ~1e-6, bench-validated (rel_err 3.4e-6 << 1e-3 across R11-R16).
__device__ __forceinline__ float fsig(float a) {
    float e = __expf(-a);
    float d = 1.0f + e;
    float y = __uint_as_float(0x7EF311C3u - __float_as_uint(d));
    y = y * (2.0f - d * y);
    y = y * (2.0f - d * y);
    return y;
}

// ---------------------------------------------------------------------------
// R16 champion + load reorder: X-gather and W LDGs issue FIRST so their
// (strided, high-latency) misses drain under the sigmoid FMA chains instead
// of serializing in front of the barrier.
// Block = (t, bc): one timestep, 8 batches. ONE block barrier.
//  Warp wid: dot (LDS.128 conflict-free) -> streams own 16KB row (__stcs).
// ---------------------------------------------------------------------------
__global__ __launch_bounds__(NT)
void gnn_fused(const float* __restrict__ X,
               const float* __restrict__ A,
               const float* __restrict__ W,
               float* __restrict__ out)
{
    __shared__ float adj[VV][AP];       // 17.4 KB
    __shared__ float xs[BPB][VV];       // 2 KB
    __shared__ float hs[BPB][VV];       // 2 KB

    const int t   = blockIdx.x;         // 0..255
    const int bc  = blockIdx.y;         // 0..7
    const int tid = threadIdx.x;
    const int wid = tid >> 5;           // 0..7 == bl
    const int lid = tid & 31;
    const int b0  = bc * BPB;

    // ---- issue high-latency loads FIRST: X gather (2 strided) + W ----
    float xr[2];
    int   xbl[2], xw[2];
    #pragma unroll
    for (int k = 0; k < (BPB * VV) / NT; ++k) {      // 2 iters, fully unrolled
        int i  = tid + k * NT;
        xbl[k] = i >> 6; xw[k] = i & 63;
        xr[k]  = X[((size_t)(b0 + xbl[k]) * VV + xw[k]) * TT + t];
    }
    const float4 wv = reinterpret_cast<const float4*>(W)[lid & 15];

    // ---- adj = fsig(A_t) off-diag, 1 on diag; 4x float4 per thread ----
    // LDG.128s issue here; sigmoid math overlaps the X/W misses above.
    const float4* Ag = reinterpret_cast<const float4*>(A + (size_t)t * VV * VV);
    #pragma unroll
    for (int k = 0; k < 4; ++k) {
        int i  = tid + k * NT;          // float4 index 0..1023, coalesced
        int v  = i >> 4;
        int w4 = i & 15;
        float4 a = Ag[i];
        float4 s;
        s.x = fsig(a.x); s.y = fsig(a.y); s.z = fsig(a.z); s.w = fsig(a.w);
        int wbase = w4 * 4;
        if (v == wbase + 0) s.x = 1.0f;
        if (v == wbase + 1) s.y = 1.0f;
        if (v == wbase + 2) s.z = 1.0f;
        if (v == wbase + 3) s.w = 1.0f;
        *reinterpret_cast<float4*>(&adj[v][wbase]) = s;
    }

    // ---- land X registers into smem just before the barrier ----
    #pragma unroll
    for (int k = 0; k < (BPB * VV) / NT; ++k)
        xs[xbl[k]][xw[k]] = xr[k];

    __syncthreads();                    // ONLY block-wide barrier

    // ---- warp-private dot: lane owns v=lid and v+32 of row bl=wid ----
    {
        float s0 = 0.f, s1 = 0.f;
        #pragma unroll
        for (int w4 = 0; w4 < 16; ++w4) {
            float4 p = *reinterpret_cast<const float4*>(&adj[lid     ][w4 * 4]); // conflict-free
            float4 q = *reinterpret_cast<const float4*>(&adj[lid + 32][w4 * 4]); // conflict-free
            float4 x = *reinterpret_cast<const float4*>(&xs[wid][w4 * 4]);       // warp bcast
            s0 = fmaf(p.x, x.x, s0); s0 = fmaf(p.y, x.y, s0);
            s0 = fmaf(p.z, x.z, s0); s0 = fmaf(p.w, x.w, s0);
            s1 = fmaf(q.x, x.x, s1); s1 = fmaf(q.y, x.y, s1);
            s1 = fmaf(q.z, x.z, s1); s1 = fmaf(q.w, x.w, s1);
        }
        hs[wid][lid]      = s0;
        hs[wid][lid + 32] = s1;
    }
    __syncwarp();                       // warp-local: hs[wid] visible to own warp

    // ---- warp streams its own 16 KB row; no block barrier -> de-staggered ----
    float4* o = reinterpret_cast<float4*>(
        out + ((size_t)(b0 + wid) * TT + t) * (VV * FF));
    #pragma unroll 8
    for (int j = 0; j < (VV * FF / 4) / 32; ++j) {   // 32 iters
        int p = j * 32 + lid;                        // float4 idx, coalesced per warp
        float h = hs[wid][p >> 4];                   // 2 distinct addrs/warp: bcast
        float4 r;
        r.x = h * wv.x; r.y = h * wv.y; r.z = h * wv.z; r.w = h * wv.w;
        r.x = fmaxf(r.x, 0.01f * r.x);               // leaky: max(x, .01x) both signs
        r.y = fmaxf(r.y, 0.01f * r.y);
        r.z = fmaxf(r.z, 0.01f * r.z);
        r.w = fmaxf(r.w, 0.01f * r.w);
        __stcs(&o[p], r);                            // evict-first stream
    }
}

extern "C" void kernel_launch(void* const* d_in, const int* in_sizes, int n_in,
                              void* d_out, int out_size) {
    const float* X = (const float*)d_in[0];   // [64, 64, 256]
    const float* A = (const float*)d_in[1];   // [256, 64, 64]
    const float* W = (const float*)d_in[2];   // [64, 1]
    float* out = (float*)d_out;               // [64, 256, 4096]
    (void)in_sizes; (void)n_in; (void)out_size;

    dim3 grid(TT, BB / BPB);                  // (256, 8) = 2048 blocks
    gnn_fused<<<grid, NT>>>(X, A, W, out);
}